// round 7
// baseline (speedup 1.0000x reference)
#include <cuda_runtime.h>
#include <cuda_bf16.h>
#include <cstdint>

// Problem constants: B=16, T=4096, D=1024, DIMS={2,2,30}
#define NTOK   65536
#define DDIM   1024
#define OUTC   34
#define NDEC   3
#define TPW    3            // tokens per warp

__device__ int g_cnt[NDEC];
__device__ int g_list[NDEC * NTOK];

// ---------------- packed f32x2 helpers (Blackwell) ----------------
static __device__ __forceinline__ unsigned long long ffma2(
    unsigned long long a, unsigned long long b, unsigned long long c) {
    unsigned long long d;
    asm("fma.rn.f32x2 %0, %1, %2, %3;" : "=l"(d) : "l"(a), "l"(b), "l"(c));
    return d;
}
static __device__ __forceinline__ float f2sum(unsigned long long v) {
    float lo, hi;
    asm("mov.b64 {%0, %1}, %2;" : "=f"(lo), "=f"(hi) : "l"(v));
    return lo + hi;
}

// ---------------- kernel 1: bucket tokens (block-aggregated atomics) ----------------
__global__ void classify_kernel(const int* __restrict__ idx) {
    __shared__ int scnt[NDEC];
    __shared__ int sbase[NDEC];
    const int tid = threadIdx.x;
    if (tid < NDEC) scnt[tid] = 0;
    __syncthreads();

    const int t = blockIdx.x * blockDim.x + tid;
    int d = 0, my = 0;
    if (t < NTOK) {
        d = idx[t];
        d = (d < 0) ? 0 : (d > 2 ? 2 : d);
        my = atomicAdd(&scnt[d], 1);           // SMEM atomic, 3 addresses
    }
    __syncthreads();
    if (tid < NDEC) sbase[tid] = atomicAdd(&g_cnt[tid], scnt[tid]);  // 3 global atomics/block
    __syncthreads();
    if (t < NTOK) g_list[d * NTOK + sbase[d] + my] = t;
}

// ---------------- kernel 2: main compute ----------------
// Persistent blocks of 384 threads (12 warps = 3/SMSP), 1 block/SM (W in SMEM).
// Each warp processes a TRIPLE of same-decoder tokens:
//   - 3 x rows in registers (24x LDG.128, coalesced, high MLP)
//   - each W shared-row load reused 3x
//   - packed f32x2 FMA; 3 interleaved butterfly reductions.
#define SMEM_FLOATS (OUTC * DDIM + OUTC + 2)
#define SMEM_BYTES  (SMEM_FLOATS * 4)

__global__ __launch_bounds__(384, 1)
void multitask_kernel(const float* __restrict__ x,
                      const float* __restrict__ W0, const float* __restrict__ b0,
                      const float* __restrict__ W1, const float* __restrict__ b1,
                      const float* __restrict__ W2, const float* __restrict__ b2,
                      float* __restrict__ out) {
    extern __shared__ float smem[];
    float* sW = smem;                 // [34][1024]: rows 0-1 W0, 2-3 W1, 4-33 W2
    float* sb = smem + OUTC * DDIM;   // [34]

    {
        float4*       dW = (float4*)sW;
        const float4* s0 = (const float4*)W0;
        const float4* s1 = (const float4*)W1;
        const float4* s2 = (const float4*)W2;
        for (int i = threadIdx.x; i < 512; i += blockDim.x)  dW[i]        = s0[i];
        for (int i = threadIdx.x; i < 512; i += blockDim.x)  dW[512 + i]  = s1[i];
        for (int i = threadIdx.x; i < 7680; i += blockDim.x) dW[1024 + i] = s2[i];
        if (threadIdx.x < 2)  sb[threadIdx.x]      = b0[threadIdx.x];
        if (threadIdx.x < 2)  sb[2 + threadIdx.x]  = b1[threadIdx.x];
        if (threadIdx.x < 30) sb[4 + threadIdx.x]  = b2[threadIdx.x];
    }
    __syncthreads();

    const int lane  = threadIdx.x & 31;
    const int warp  = threadIdx.x >> 5;
    const int gw    = blockIdx.x * (blockDim.x >> 5) + warp;
    const int nwrp  = gridDim.x * (blockDim.x >> 5);

    const int c0 = g_cnt[0], c1 = g_cnt[1], c2 = g_cnt[2];
    const int P0 = (c0 + TPW - 1) / TPW, P1 = (c1 + TPW - 1) / TPW,
              P2 = (c2 + TPW - 1) / TPW;
    const int TP = P0 + P1 + P2;

    const ulonglong2* X = (const ulonglong2*)x;   // 16B chunks; 256 per row

    for (int p = gw; p < TP; p += nwrp) {
        int d, lp, cnt;
        if (p < P0)            { d = 0; lp = p;            cnt = c0; }
        else if (p < P0 + P1)  { d = 1; lp = p - P0;       cnt = c1; }
        else                   { d = 2; lp = p - P0 - P1;  cnt = c2; }
        const int base = (d == 0) ? 0 : (d == 1) ? 2 : 4;
        const int dim  = (d == 2) ? 30 : 2;

        const int q = TPW * lp;
        int  tok[TPW];
        bool has[TPW];
        #pragma unroll
        for (int i = 0; i < TPW; i++) {
            int j = q + i;
            has[i] = (j < cnt);
            tok[i] = g_list[d * NTOK + (has[i] ? j : q)];
        }

        // 3 x rows into registers: 24x LDG.128 per warp.
        ulonglong2 xr[TPW][8];
        #pragma unroll
        for (int i = 0; i < TPW; i++) {
            const ulonglong2* XR = X + (size_t)tok[i] * 256;
            #pragma unroll
            for (int j = 0; j < 8; j++) xr[i][j] = XR[j * 32 + lane];
        }

        float r0[TPW] = {0.f, 0.f, 0.f};
        float r1[TPW] = {0.f, 0.f, 0.f};
        const ulonglong2* Wp = (const ulonglong2*)(sW + base * DDIM);

        #pragma unroll 2
        for (int o = 0; o < dim; o++) {
            const ulonglong2* wrow = Wp + o * 256;  // 1024 floats = 256 x 16B
            unsigned long long a0[TPW] = {0, 0, 0};
            unsigned long long a1[TPW] = {0, 0, 0};
            #pragma unroll
            for (int j = 0; j < 8; j++) {
                ulonglong2 w = wrow[j * 32 + lane];  // LDS.128, conflict-free
                #pragma unroll
                for (int i = 0; i < TPW; i++) {
                    a0[i] = ffma2(xr[i][j].x, w.x, a0[i]);
                    a1[i] = ffma2(xr[i][j].y, w.y, a1[i]);
                }
            }
            float v[TPW];
            #pragma unroll
            for (int i = 0; i < TPW; i++) v[i] = f2sum(a0[i]) + f2sum(a1[i]);
            // interleaved butterfly reductions (SHFL latency overlapped)
            #pragma unroll
            for (int s = 16; s > 0; s >>= 1) {
                #pragma unroll
                for (int i = 0; i < TPW; i++)
                    v[i] += __shfl_xor_sync(0xFFFFFFFFu, v[i], s);
            }
            const int oi = base + o;
            const float bias = sb[oi];
            #pragma unroll
            for (int i = 0; i < TPW; i++) {
                float vi = v[i] + bias;
                if (oi == lane)      r0[i] = vi;
                if (oi - 32 == lane) r1[i] = vi;
            }
        }

        // Write all 34 channels (non-selected decoders = 0, matching reference).
        #pragma unroll
        for (int i = 0; i < TPW; i++) {
            if (has[i]) {
                float* o_ = out + (size_t)tok[i] * OUTC;
                o_[lane] = r0[i];
                if (lane < 2) o_[32 + lane] = r1[i];
            }
        }
    }
}

extern "C" void kernel_launch(void* const* d_in, const int* in_sizes, int n_in,
                              void* d_out, int out_size) {
    const float* x   = (const float*)d_in[0];
    const int*   idx = (const int*)  d_in[1];
    const float* W0  = (const float*)d_in[2];
    const float* b0  = (const float*)d_in[3];
    const float* W1  = (const float*)d_in[4];
    const float* b1  = (const float*)d_in[5];
    const float* W2  = (const float*)d_in[6];
    const float* b2  = (const float*)d_in[7];
    float* out = (float*)d_out;

    cudaFuncSetAttribute(multitask_kernel,
                         cudaFuncAttributeMaxDynamicSharedMemorySize, SMEM_BYTES);

    // Zero the bucket counters with a memset node (cheaper than a kernel launch).
    void* cnt_ptr = nullptr;
    cudaGetSymbolAddress(&cnt_ptr, g_cnt);
    cudaMemsetAsync(cnt_ptr, 0, NDEC * sizeof(int), 0);

    classify_kernel<<<(NTOK + 511) / 512, 512>>>(idx);
    multitask_kernel<<<148, 384, SMEM_BYTES>>>(x, W0, b0, W1, b1, W2, b2, out);
}